// round 5
// baseline (speedup 1.0000x reference)
#include <cuda_runtime.h>
#include <cuda_bf16.h>
#include <cstdint>

// Problem dims (fixed by the reference)
#define MD 4096   // B*T
#define HD 4096   // hidden
#define SD 1024   // sampled intermediate
#define FD 9984   // ffn intermediate
#define GD 6      // taylor orders
#define KT 7168   // (G+1)*S concat-K for the fused Taylor GEMM

// -------- device scratch (no cudaMalloc allowed) --------
__device__ float g_gate[(size_t)MD * SD];
__device__ float g_T   [(size_t)MD * KT];   // order-0 block doubles as approx_up storage
__device__ float g_W   [(size_t)HD * KT];
__device__ float g_G   [(size_t)MD * FD];
__device__ float g_U   [(size_t)MD * FD];

// -------- bf16x3 split GEMM: C[M,N] (+)= A[M,K] * B[N,K]^T, row-major fp32 in/out --------
// Each fp32 x is split as hi=bf16(x), lo=bf16(x-hi). Three MMA passes:
// hi*hi + hi*lo + lo*hi (lo*lo ~2^-18 relative, dropped). fp32 accumulators.
#define BM 128
#define BN 128
#define BK 32
#define LDSW 20         // pad 16->20 words: fragment LDS conflict-free (r*20 mod 32 spans all banks)
#define TILE_W (BM * LDSW)               // words per tile buffer
#define SMEM_WORDS (8 * TILE_W)          // {A,B} x {hi,lo} x double-buffer
#define SMEM_BYTES (SMEM_WORDS * 4)      // 81920 B

__device__ __forceinline__ void mma16(float* d, const uint32_t* a, const uint32_t* b) {
    asm volatile(
        "mma.sync.aligned.m16n8k16.row.col.f32.bf16.bf16.f32 "
        "{%0,%1,%2,%3}, {%4,%5,%6,%7}, {%8,%9}, {%0,%1,%2,%3};\n"
        : "+f"(d[0]), "+f"(d[1]), "+f"(d[2]), "+f"(d[3])
        : "r"(a[0]), "r"(a[1]), "r"(a[2]), "r"(a[3]), "r"(b[0]), "r"(b[1]));
}

// split 4 consecutive fp32 (k-dim) into 2 bf16x2 hi words + 2 lo words
__device__ __forceinline__ void split4(float4 v, uint32_t* hi2, uint32_t* lo2) {
    __nv_bfloat16 hx = __float2bfloat16_rn(v.x);
    __nv_bfloat16 hy = __float2bfloat16_rn(v.y);
    __nv_bfloat16 hz = __float2bfloat16_rn(v.z);
    __nv_bfloat16 hw = __float2bfloat16_rn(v.w);
    __nv_bfloat16 lx = __float2bfloat16_rn(v.x - __bfloat162float(hx));
    __nv_bfloat16 ly = __float2bfloat16_rn(v.y - __bfloat162float(hy));
    __nv_bfloat16 lz = __float2bfloat16_rn(v.z - __bfloat162float(hz));
    __nv_bfloat16 lw = __float2bfloat16_rn(v.w - __bfloat162float(hw));
    __nv_bfloat162 h0 = __nv_bfloat162(hx, hy), h1 = __nv_bfloat162(hz, hw);
    __nv_bfloat162 l0 = __nv_bfloat162(lx, ly), l1 = __nv_bfloat162(lz, lw);
    hi2[0] = *reinterpret_cast<uint32_t*>(&h0);
    hi2[1] = *reinterpret_cast<uint32_t*>(&h1);
    lo2[0] = *reinterpret_cast<uint32_t*>(&l0);
    lo2[1] = *reinterpret_cast<uint32_t*>(&l1);
}

__global__ void __launch_bounds__(256, 1)
gemm_bf16x3(const float* __restrict__ A, int lda,
            const float* __restrict__ B, int ldb,
            float* __restrict__ C, int ldc,
            int M, int N, int K, int accumulate) {
    extern __shared__ uint32_t sm[];
    const int tid = threadIdx.x;

    // L2-friendly tile rasterization (GROUP along M)
    const int grid_m = M / BM, grid_n = N / BN;
    const int GROUP = 16;
    int pid   = blockIdx.x;
    int width = GROUP * grid_n;
    int group = pid / width;
    int first = group * GROUP;
    int gsz   = min(GROUP, grid_m - first);
    int tm    = first + (pid % gsz);
    int tn    = (pid % width) / gsz;
    const int m0 = tm * BM, n0 = tn * BN;

    uint32_t* sAhi = sm;                 // 2 * TILE_W (double buffered)
    uint32_t* sAlo = sm + 2 * TILE_W;
    uint32_t* sBhi = sm + 4 * TILE_W;
    uint32_t* sBlo = sm + 6 * TILE_W;

    // global tile load mapping: 256 threads, rows tid>>3 (+i*32), float4 at col (tid&7)*4
    const int lrow = tid >> 3;           // 0..31
    const int lcol = (tid & 7) * 4;      // fp32 col 0..28
    const int wcol = (tid & 7) * 2;      // bf16x2 word col 0..14
    const float* gA = A + (size_t)(m0 + lrow) * lda + lcol;
    const float* gB = B + (size_t)(n0 + lrow) * ldb + lcol;

    float4 pa[4], pb[4];
#pragma unroll
    for (int i = 0; i < 4; i++) {
        pa[i] = *reinterpret_cast<const float4*>(gA + (size_t)(i * 32) * lda);
        pb[i] = *reinterpret_cast<const float4*>(gB + (size_t)(i * 32) * ldb);
    }
#pragma unroll
    for (int i = 0; i < 4; i++) {
        uint32_t h[2], l[2];
        int base = (lrow + i * 32) * LDSW + wcol;
        split4(pa[i], h, l);
        *reinterpret_cast<uint2*>(&sAhi[base]) = make_uint2(h[0], h[1]);
        *reinterpret_cast<uint2*>(&sAlo[base]) = make_uint2(l[0], l[1]);
        split4(pb[i], h, l);
        *reinterpret_cast<uint2*>(&sBhi[base]) = make_uint2(h[0], h[1]);
        *reinterpret_cast<uint2*>(&sBlo[base]) = make_uint2(l[0], l[1]);
    }
    __syncthreads();

    const int lane = tid & 31;
    const int warp = tid >> 5;
    const int wm = (warp & 1) * 64;   // 2 warps along M -> 64 rows each
    const int wn = (warp >> 1) * 32;  // 4 warps along N -> 32 cols each
    const int r  = lane >> 2;         // group id
    const int cc = lane & 3;          // thread in group

    float acc[4][4][4];
#pragma unroll
    for (int i = 0; i < 4; i++)
#pragma unroll
        for (int j = 0; j < 4; j++)
#pragma unroll
            for (int k = 0; k < 4; k++) acc[i][j][k] = 0.f;

    const int Kt = K / BK;
    for (int kt = 0; kt < Kt; kt++) {
        if (kt + 1 < Kt) {
            const float* a2 = gA + (size_t)(kt + 1) * BK;
            const float* b2 = gB + (size_t)(kt + 1) * BK;
#pragma unroll
            for (int i = 0; i < 4; i++) {
                pa[i] = *reinterpret_cast<const float4*>(a2 + (size_t)(i * 32) * lda);
                pb[i] = *reinterpret_cast<const float4*>(b2 + (size_t)(i * 32) * ldb);
            }
        }
        const uint32_t* Ah = sAhi + (kt & 1) * TILE_W;
        const uint32_t* Al = sAlo + (kt & 1) * TILE_W;
        const uint32_t* Bh = sBhi + (kt & 1) * TILE_W;
        const uint32_t* Bl = sBlo + (kt & 1) * TILE_W;
#pragma unroll
        for (int kk = 0; kk < 2; kk++) {   // two k16 chunks per BK=32
            uint32_t afh[4][4], afl[4][4], bfh[4][2], bfl[4][2];
            const int kw = kk * 8 + cc;
#pragma unroll
            for (int mf = 0; mf < 4; mf++) {
                int a0 = (wm + mf * 16 + r) * LDSW + kw;
                int a1 = a0 + 8 * LDSW;
                afh[mf][0] = Ah[a0];     afh[mf][1] = Ah[a1];
                afh[mf][2] = Ah[a0 + 4]; afh[mf][3] = Ah[a1 + 4];
                afl[mf][0] = Al[a0];     afl[mf][1] = Al[a1];
                afl[mf][2] = Al[a0 + 4]; afl[mf][3] = Al[a1 + 4];
            }
#pragma unroll
            for (int nf = 0; nf < 4; nf++) {
                int b0 = (wn + nf * 8 + r) * LDSW + kw;
                bfh[nf][0] = Bh[b0]; bfh[nf][1] = Bh[b0 + 4];
                bfl[nf][0] = Bl[b0]; bfl[nf][1] = Bl[b0 + 4];
            }
#pragma unroll
            for (int mf = 0; mf < 4; mf++)
#pragma unroll
                for (int nf = 0; nf < 4; nf++) {
                    mma16(acc[mf][nf], afh[mf], bfh[nf]);   // hi*hi
                    mma16(acc[mf][nf], afh[mf], bfl[nf]);   // hi*lo
                    mma16(acc[mf][nf], afl[mf], bfh[nf]);   // lo*hi
                }
        }
        if (kt + 1 < Kt) {
            uint32_t* Anh = sAhi + ((kt + 1) & 1) * TILE_W;
            uint32_t* Anl = sAlo + ((kt + 1) & 1) * TILE_W;
            uint32_t* Bnh = sBhi + ((kt + 1) & 1) * TILE_W;
            uint32_t* Bnl = sBlo + ((kt + 1) & 1) * TILE_W;
#pragma unroll
            for (int i = 0; i < 4; i++) {
                uint32_t h[2], l[2];
                int base = (lrow + i * 32) * LDSW + wcol;
                split4(pa[i], h, l);
                *reinterpret_cast<uint2*>(&Anh[base]) = make_uint2(h[0], h[1]);
                *reinterpret_cast<uint2*>(&Anl[base]) = make_uint2(l[0], l[1]);
                split4(pb[i], h, l);
                *reinterpret_cast<uint2*>(&Bnh[base]) = make_uint2(h[0], h[1]);
                *reinterpret_cast<uint2*>(&Bnl[base]) = make_uint2(l[0], l[1]);
            }
        }
        __syncthreads();
    }

    // epilogue (m16n8 f32 accumulator layout)
#pragma unroll
    for (int mf = 0; mf < 4; mf++) {
#pragma unroll
        for (int nf = 0; nf < 4; nf++) {
            int grow = m0 + wm + mf * 16 + r;
            int gcol = n0 + wn + nf * 8 + cc * 2;
            float* c0 = C + (size_t)grow * ldc + gcol;
            float* c1 = C + (size_t)(grow + 8) * ldc + gcol;
            if (accumulate) {
                float2 v0 = *reinterpret_cast<float2*>(c0);
                float2 v1 = *reinterpret_cast<float2*>(c1);
                v0.x += acc[mf][nf][0]; v0.y += acc[mf][nf][1];
                v1.x += acc[mf][nf][2]; v1.y += acc[mf][nf][3];
                *reinterpret_cast<float2*>(c0) = v0;
                *reinterpret_cast<float2*>(c1) = v1;
            } else {
                *reinterpret_cast<float2*>(c0) = make_float2(acc[mf][nf][0], acc[mf][nf][1]);
                *reinterpret_cast<float2*>(c1) = make_float2(acc[mf][nf][2], acc[mf][nf][3]);
            }
        }
    }
}

// -------- elementwise: fill Tcat[bt, g*S+s] = (delta^g / g!) * approx_up (cutoff g=5,6) --------
// approx_up already sits in the order-0 block g_T[bt*KT + s] (GEMM wrote it there, ldc=KT).
__global__ void build_T_kernel(const float* __restrict__ lp) {
    int i = blockIdx.x * blockDim.x + threadIdx.x;   // over MD*SD
    int s  = i & (SD - 1);
    int bt = i >> 10;
    size_t base = (size_t)bt * KT + s;
    float au = g_T[base];
    float d  = g_gate[i] - lp[s];
    float keep = (fabsf(d) <= 2.5f) ? 1.0f : 0.0f;
    float p = 1.0f;
    p *= d;                g_T[base + 1 * SD] = p * au;          // d
    p *= d * 0.5f;         g_T[base + 2 * SD] = p * au;          // d^2/2
    p *= d * (1.f / 3.f);  g_T[base + 3 * SD] = p * au;          // d^3/6
    p *= d * 0.25f;        g_T[base + 4 * SD] = p * au;          // d^4/24
    p *= d * 0.2f;         g_T[base + 5 * SD] = p * au * keep;   // d^5/120 (cutoff)
    p *= d * (1.f / 6.f);  g_T[base + 6 * SD] = p * au * keep;   // d^6/720 (cutoff)
}

// -------- pack Wcat[h, g*S+s]: g=0 -> local_approx_output[h,s]; g>=1 -> fuse_weight[h,s,g-1] --------
__global__ void pack_W_kernel(const float* __restrict__ la, const float* __restrict__ fw) {
    int h = blockIdx.x;
    __shared__ float tile[SD * GD];   // 6144 floats = 24KB
    const float* src = fw + (size_t)h * SD * GD;
    for (int i = threadIdx.x; i < SD * GD; i += blockDim.x) tile[i] = src[i];   // coalesced
    float* dst = g_W + (size_t)h * KT;
    for (int i = threadIdx.x; i < SD; i += blockDim.x) dst[i] = la[(size_t)h * SD + i];
    __syncthreads();
    for (int j = threadIdx.x; j < SD * GD; j += blockDim.x) {
        int g = j >> 10, s = j & (SD - 1);
        dst[SD + j] = tile[s * GD + g];   // write coalesced; smem read stride-6 (mild conflict)
    }
}

// -------- elementwise: act = silu(G) * U, in place over g_G --------
__global__ void act_kernel() {
    size_t i = (size_t)blockIdx.x * blockDim.x + threadIdx.x;
    float g = g_G[i], u = g_U[i];
    g_G[i] = u * g / (1.0f + __expf(-g));
}

// -------- launcher --------
extern "C" void kernel_launch(void* const* d_in, const int* in_sizes, int n_in,
                              void* d_out, int out_size) {
    (void)in_sizes; (void)n_in; (void)out_size;
    const float* hidden = (const float*)d_in[0];   // [B,T,H]
    const float* up_w   = (const float*)d_in[1];   // [S,H]
    const float* gate_w = (const float*)d_in[2];   // [S,H]
    const float* lp     = (const float*)d_in[3];   // [S]
    const float* la     = (const float*)d_in[4];   // [H,S]
    const float* fw     = (const float*)d_in[5];   // [H,S,G]
    // d_in[6] = discount_factor: factorials computed directly
    const float* fg     = (const float*)d_in[7];   // [F,H]
    const float* fu     = (const float*)d_in[8];   // [F,H]
    const float* fd     = (const float*)d_in[9];   // [H,F]
    float* out = (float*)d_out;                    // [B,T,H] fp32

    float *p_gate, *p_T, *p_W, *p_G, *p_U;
    cudaGetSymbolAddress((void**)&p_gate, g_gate);
    cudaGetSymbolAddress((void**)&p_T,    g_T);
    cudaGetSymbolAddress((void**)&p_W,    g_W);
    cudaGetSymbolAddress((void**)&p_G,    g_G);
    cudaGetSymbolAddress((void**)&p_U,    g_U);

    cudaFuncSetAttribute(gemm_bf16x3, cudaFuncAttributeMaxDynamicSharedMemorySize, SMEM_BYTES);

    auto gemm = [&](const float* A, int lda, const float* B, int ldb,
                    float* C, int ldc, int M, int N, int K, int accum) {
        int blocks = (M / BM) * (N / BN);
        gemm_bf16x3<<<blocks, 256, SMEM_BYTES>>>(A, lda, B, ldb, C, ldc, M, N, K, accum);
    };

    // Taylor path
    gemm(hidden, HD, up_w,   HD, p_T,    KT, MD, SD, HD, 0);   // approx_up -> order-0 block of Tcat
    gemm(hidden, HD, gate_w, HD, p_gate, SD, MD, SD, HD, 0);   // gate_pre
    build_T_kernel<<<(MD * SD) / 256, 256>>>(lp);
    pack_W_kernel<<<HD, 256>>>(la, fw);
    gemm(p_T, KT, p_W, KT, out, HD, MD, HD, KT, 0);            // approx_out (writes out)

    // FFN path
    gemm(hidden, HD, fg, HD, p_G, FD, MD, FD, HD, 0);          // gate pre-act
    gemm(hidden, HD, fu, HD, p_U, FD, MD, FD, HD, 0);          // up
    act_kernel<<<(int)(((size_t)MD * FD) / 256), 256>>>();     // silu(G)*U -> g_G
    gemm(p_G, FD, fd, FD, out, HD, MD, HD, FD, 1);             // accumulate into out
}

// round 9
// speedup vs baseline: 1.3694x; 1.3694x over previous
#include <cuda_runtime.h>
#include <cuda_bf16.h>
#include <cstdint>

// Problem dims (fixed by the reference)
#define MD 4096   // B*T
#define HD 4096   // hidden
#define SD 1024   // sampled intermediate
#define FD 9984   // ffn intermediate
#define GD 6      // taylor orders
#define KT 7168   // (G+1)*S concat-K for the fused Taylor GEMM

// -------- device scratch (no cudaMalloc allowed) --------
// fp32 intermediates
__device__ float g_up  [(size_t)MD * SD];
__device__ float g_gate[(size_t)MD * SD];
__device__ float g_G   [(size_t)MD * FD];
__device__ float g_U   [(size_t)MD * FD];
// bf16 hi/lo operand planes (split once; GEMMs read these directly)
__device__ __align__(16) __nv_bfloat16 g_Hh [(size_t)MD * HD];
__device__ __align__(16) __nv_bfloat16 g_Hl [(size_t)MD * HD];
__device__ __align__(16) __nv_bfloat16 g_UPh[(size_t)SD * HD];
__device__ __align__(16) __nv_bfloat16 g_UPl[(size_t)SD * HD];
__device__ __align__(16) __nv_bfloat16 g_GWh[(size_t)SD * HD];
__device__ __align__(16) __nv_bfloat16 g_GWl[(size_t)SD * HD];
__device__ __align__(16) __nv_bfloat16 g_Th [(size_t)MD * KT];
__device__ __align__(16) __nv_bfloat16 g_Tl [(size_t)MD * KT];
__device__ __align__(16) __nv_bfloat16 g_Wh [(size_t)HD * KT];
__device__ __align__(16) __nv_bfloat16 g_Wl [(size_t)HD * KT];
__device__ __align__(16) __nv_bfloat16 g_FGh[(size_t)FD * HD];
__device__ __align__(16) __nv_bfloat16 g_FGl[(size_t)FD * HD];
__device__ __align__(16) __nv_bfloat16 g_FUh[(size_t)FD * HD];
__device__ __align__(16) __nv_bfloat16 g_FUl[(size_t)FD * HD];
__device__ __align__(16) __nv_bfloat16 g_FDh[(size_t)HD * FD];
__device__ __align__(16) __nv_bfloat16 g_FDl[(size_t)HD * FD];
__device__ __align__(16) __nv_bfloat16 g_Ah [(size_t)MD * FD];
__device__ __align__(16) __nv_bfloat16 g_Al [(size_t)MD * FD];

// ======================= helpers =======================
__device__ __forceinline__ uint32_t smem_u32(const void* p) {
    uint32_t a;
    asm("{ .reg .u64 t; cvta.to.shared.u64 t, %1; cvt.u32.u64 %0, t; }" : "=r"(a) : "l"(p));
    return a;
}
__device__ __forceinline__ void cpa16(uint32_t dst, const void* src) {
    asm volatile("cp.async.cg.shared.global [%0], [%1], 16;" :: "r"(dst), "l"(src));
}
#define CP_COMMIT() asm volatile("cp.async.commit_group;" ::: "memory")
#define CP_WAIT1()  asm volatile("cp.async.wait_group 1;" ::: "memory")

__device__ __forceinline__ void mma16(float* d, const uint32_t* a, const uint32_t* b) {
    asm volatile(
        "mma.sync.aligned.m16n8k16.row.col.f32.bf16.bf16.f32 "
        "{%0,%1,%2,%3}, {%4,%5,%6,%7}, {%8,%9}, {%0,%1,%2,%3};\n"
        : "+f"(d[0]), "+f"(d[1]), "+f"(d[2]), "+f"(d[3])
        : "r"(a[0]), "r"(a[1]), "r"(a[2]), "r"(a[3]), "r"(b[0]), "r"(b[1]));
}

__device__ __forceinline__ void wsplit(__nv_bfloat16* hp, __nv_bfloat16* lp, size_t idx, float v) {
    __nv_bfloat16 h = __float2bfloat16_rn(v);
    hp[idx] = h;
    lp[idx] = __float2bfloat16_rn(v - __bfloat162float(h));
}

// ======================= bf16x3 GEMM on pre-split planes =======================
// C[M,N] (+)= A[M,K] * B[N,K]^T; A,B given as bf16 hi/lo planes, C fp32.
// D += Ahi*Bhi + Ahi*Blo + Alo*Bhi (fp32 accum). 128x128 tile, BK=32,
// 3-stage cp.async pipeline, padded smem (LDSW=20 words) — conflict-free frags.
#define BK 32
#define LDSW 20                     // 16 data words (32 bf16) + 4 pad
#define PLW (128 * LDSW)            // words per plane = 2560
#define STW (4 * PLW)               // words per stage (Ahi,Alo,Bhi,Blo) = 10240
#define NSTAGE 3
#define SMEM_BYTES (NSTAGE * STW * 4)   // 122880

__global__ void __launch_bounds__(256, 1)
gemm_planes(const __nv_bfloat16* __restrict__ Ah, const __nv_bfloat16* __restrict__ Al, int lda,
            const __nv_bfloat16* __restrict__ Bh, const __nv_bfloat16* __restrict__ Bl, int ldb,
            float* __restrict__ C, int ldc, int M, int N, int K, int accumulate) {
    extern __shared__ uint32_t smw[];
    const uint32_t sbase = smem_u32(smw);
    const int tid = threadIdx.x;

    // L2-friendly tile rasterization (GROUP along M)
    const int grid_m = M / 128, grid_n = N / 128;
    const int GROUP = 16;
    int pid   = blockIdx.x;
    int width = GROUP * grid_n;
    int group = pid / width;
    int first = group * GROUP;
    int gsz   = min(GROUP, grid_m - first);
    int tm    = first + (pid % gsz);
    int tn    = (pid % width) / gsz;
    const int m0 = tm * 128, n0 = tn * 128;

    // cp.async fill mapping: row = tid>>1 (0..127), half = tid&1 (2 x 16B per plane)
    const int frow = tid >> 1;
    const int fhalf = tid & 1;
    const __nv_bfloat16* pAh = Ah + (size_t)(m0 + frow) * lda + fhalf * 16;
    const __nv_bfloat16* pAl = Al + (size_t)(m0 + frow) * lda + fhalf * 16;
    const __nv_bfloat16* pBh = Bh + (size_t)(n0 + frow) * ldb + fhalf * 16;
    const __nv_bfloat16* pBl = Bl + (size_t)(n0 + frow) * ldb + fhalf * 16;
    const uint32_t dstw0 = (frow * LDSW + fhalf * 8) * 4;   // byte offset within plane

    const int Kt = K / BK;

    auto issue = [&](int kt) {
        const int k0 = kt * BK;
        uint32_t d = sbase + (kt % NSTAGE) * (STW * 4) + dstw0;
        cpa16(d, pAh + k0);            cpa16(d + 16, pAh + k0 + 8);
        d += PLW * 4;
        cpa16(d, pAl + k0);            cpa16(d + 16, pAl + k0 + 8);
        d += PLW * 4;
        cpa16(d, pBh + k0);            cpa16(d + 16, pBh + k0 + 8);
        d += PLW * 4;
        cpa16(d, pBl + k0);            cpa16(d + 16, pBl + k0 + 8);
    };

    // prologue: stages 0 and 1 in flight (Kt >= 2 always here)
    issue(0); CP_COMMIT();
    issue(1); CP_COMMIT();

    const int lane = tid & 31;
    const int warp = tid >> 5;
    const int wm = (warp & 1) * 64;   // 2 warps along M -> 64 rows each
    const int wn = (warp >> 1) * 32;  // 4 warps along N -> 32 cols each
    const int r  = lane >> 2;
    const int cc = lane & 3;

    float acc[4][4][4];
#pragma unroll
    for (int i = 0; i < 4; i++)
#pragma unroll
        for (int j = 0; j < 4; j++)
#pragma unroll
            for (int k = 0; k < 4; k++) acc[i][j][k] = 0.f;

    for (int kt = 0; kt < Kt; kt++) {
        CP_WAIT1();              // stage kt data complete (<=1 newer group pending)
        __syncthreads();         // visibility + everyone done computing kt-1
        if (kt + 2 < Kt) issue(kt + 2);
        CP_COMMIT();             // exactly one group per iteration (may be empty)

        const uint32_t* Ahs = smw + (kt % NSTAGE) * STW;
        const uint32_t* Als = Ahs + PLW;
        const uint32_t* Bhs = Ahs + 2 * PLW;
        const uint32_t* Bls = Ahs + 3 * PLW;
#pragma unroll
        for (int kk = 0; kk < 2; kk++) {   // two k16 chunks per BK=32
            uint32_t afh[4][4], afl[4][4], bfh[4][2], bfl[4][2];
            const int kw = kk * 8 + cc;
#pragma unroll
            for (int mf = 0; mf < 4; mf++) {
                int a0 = (wm + mf * 16 + r) * LDSW + kw;
                int a1 = a0 + 8 * LDSW;
                afh[mf][0] = Ahs[a0];     afh[mf][1] = Ahs[a1];
                afh[mf][2] = Ahs[a0 + 4]; afh[mf][3] = Ahs[a1 + 4];
                afl[mf][0] = Als[a0];     afl[mf][1] = Als[a1];
                afl[mf][2] = Als[a0 + 4]; afl[mf][3] = Als[a1 + 4];
            }
#pragma unroll
            for (int nf = 0; nf < 4; nf++) {
                int b0 = (wn + nf * 8 + r) * LDSW + kw;
                bfh[nf][0] = Bhs[b0]; bfh[nf][1] = Bhs[b0 + 4];
                bfl[nf][0] = Bls[b0]; bfl[nf][1] = Bls[b0 + 4];
            }
#pragma unroll
            for (int mf = 0; mf < 4; mf++)
#pragma unroll
                for (int nf = 0; nf < 4; nf++) {
                    mma16(acc[mf][nf], afh[mf], bfh[nf]);   // hi*hi
                    mma16(acc[mf][nf], afh[mf], bfl[nf]);   // hi*lo
                    mma16(acc[mf][nf], afl[mf], bfh[nf]);   // lo*hi
                }
        }
    }

    // epilogue (m16n8 f32 accumulator layout)
#pragma unroll
    for (int mf = 0; mf < 4; mf++) {
#pragma unroll
        for (int nf = 0; nf < 4; nf++) {
            int grow = m0 + wm + mf * 16 + r;
            int gcol = n0 + wn + nf * 8 + cc * 2;
            float* c0 = C + (size_t)grow * ldc + gcol;
            float* c1 = C + (size_t)(grow + 8) * ldc + gcol;
            if (accumulate) {
                float2 v0 = *reinterpret_cast<float2*>(c0);
                float2 v1 = *reinterpret_cast<float2*>(c1);
                v0.x += acc[mf][nf][0]; v0.y += acc[mf][nf][1];
                v1.x += acc[mf][nf][2]; v1.y += acc[mf][nf][3];
                *reinterpret_cast<float2*>(c0) = v0;
                *reinterpret_cast<float2*>(c1) = v1;
            } else {
                *reinterpret_cast<float2*>(c0) = make_float2(acc[mf][nf][0], acc[mf][nf][1]);
                *reinterpret_cast<float2*>(c1) = make_float2(acc[mf][nf][2], acc[mf][nf][3]);
            }
        }
    }
}

// -------- one-time fp32 -> bf16 hi/lo plane split (vectorized) --------
__global__ void split_kernel(const float* __restrict__ src,
                             __nv_bfloat16* __restrict__ hi,
                             __nv_bfloat16* __restrict__ lo) {
    size_t i = ((size_t)blockIdx.x * 256 + threadIdx.x) * 4;
    float4 v = *reinterpret_cast<const float4*>(src + i);
    __nv_bfloat16 h0 = __float2bfloat16_rn(v.x), h1 = __float2bfloat16_rn(v.y);
    __nv_bfloat16 h2 = __float2bfloat16_rn(v.z), h3 = __float2bfloat16_rn(v.w);
    __nv_bfloat16 l0 = __float2bfloat16_rn(v.x - __bfloat162float(h0));
    __nv_bfloat16 l1 = __float2bfloat16_rn(v.y - __bfloat162float(h1));
    __nv_bfloat16 l2 = __float2bfloat16_rn(v.z - __bfloat162float(h2));
    __nv_bfloat16 l3 = __float2bfloat16_rn(v.w - __bfloat162float(h3));
    __nv_bfloat162 H0(h0, h1), H1(h2, h3), L0(l0, l1), L1(l2, l3);
    *reinterpret_cast<uint2*>(hi + i) =
        make_uint2(*reinterpret_cast<uint32_t*>(&H0), *reinterpret_cast<uint32_t*>(&H1));
    *reinterpret_cast<uint2*>(lo + i) =
        make_uint2(*reinterpret_cast<uint32_t*>(&L0), *reinterpret_cast<uint32_t*>(&L1));
}

// -------- build Tcat planes: T[bt, g*S+s] = (delta^g / g!) * approx_up (cutoff g=5,6) --------
__global__ void build_T_kernel(const float* __restrict__ lp) {
    int i = blockIdx.x * blockDim.x + threadIdx.x;   // over MD*SD
    int s  = i & (SD - 1);
    int bt = i >> 10;
    size_t base = (size_t)bt * KT + s;
    float au = g_up[i];
    float d  = g_gate[i] - lp[s];
    float keep = (fabsf(d) <= 2.5f) ? 1.0f : 0.0f;
    float p = 1.0f;
    wsplit(g_Th, g_Tl, base, au);                                  // order 0
    p *= d;                wsplit(g_Th, g_Tl, base + 1 * SD, p * au);
    p *= d * 0.5f;         wsplit(g_Th, g_Tl, base + 2 * SD, p * au);
    p *= d * (1.f / 3.f);  wsplit(g_Th, g_Tl, base + 3 * SD, p * au);
    p *= d * 0.25f;        wsplit(g_Th, g_Tl, base + 4 * SD, p * au);
    p *= d * 0.2f;         wsplit(g_Th, g_Tl, base + 5 * SD, p * au * keep);
    p *= d * (1.f / 6.f);  wsplit(g_Th, g_Tl, base + 6 * SD, p * au * keep);
}

// -------- pack Wcat planes: g=0 -> local_approx_output[h,s]; g>=1 -> fuse_weight[h,s,g-1] --------
__global__ void pack_W_kernel(const float* __restrict__ la, const float* __restrict__ fw) {
    int h = blockIdx.x;
    __shared__ float tile[SD * GD];   // 24KB
    const float* src = fw + (size_t)h * SD * GD;
    for (int i = threadIdx.x; i < SD * GD; i += blockDim.x) tile[i] = src[i];   // coalesced
    size_t dstb = (size_t)h * KT;
    for (int i = threadIdx.x; i < SD; i += blockDim.x)
        wsplit(g_Wh, g_Wl, dstb + i, la[(size_t)h * SD + i]);
    __syncthreads();
    for (int j = threadIdx.x; j < SD * GD; j += blockDim.x) {
        int g = j >> 10, s = j & (SD - 1);
        wsplit(g_Wh, g_Wl, dstb + SD + j, tile[s * GD + g]);
    }
}

// -------- act planes: silu(G) * U --------
__global__ void act_kernel() {
    size_t i = (size_t)blockIdx.x * blockDim.x + threadIdx.x;
    float g = g_G[i], u = g_U[i];
    float v = u * g / (1.0f + __expf(-g));
    wsplit(g_Ah, g_Al, i, v);
}

// -------- launcher --------
extern "C" void kernel_launch(void* const* d_in, const int* in_sizes, int n_in,
                              void* d_out, int out_size) {
    (void)in_sizes; (void)n_in; (void)out_size;
    const float* hidden = (const float*)d_in[0];   // [B,T,H]
    const float* up_w   = (const float*)d_in[1];   // [S,H]
    const float* gate_w = (const float*)d_in[2];   // [S,H]
    const float* lp     = (const float*)d_in[3];   // [S]
    const float* la     = (const float*)d_in[4];   // [H,S]
    const float* fw     = (const float*)d_in[5];   // [H,S,G]
    // d_in[6] = discount_factor: factorials computed directly
    const float* fg     = (const float*)d_in[7];   // [F,H]
    const float* fu     = (const float*)d_in[8];   // [F,H]
    const float* fd     = (const float*)d_in[9];   // [H,F]
    float* out = (float*)d_out;                    // [B,T,H] fp32

    float *p_up, *p_gate, *p_G, *p_U;
    __nv_bfloat16 *Hh, *Hl, *UPh, *UPl, *GWh, *GWl, *Th, *Tl, *Wh, *Wl;
    __nv_bfloat16 *FGh, *FGl, *FUh, *FUl, *FDh, *FDl, *Ah, *Al;
    cudaGetSymbolAddress((void**)&p_up,   g_up);
    cudaGetSymbolAddress((void**)&p_gate, g_gate);
    cudaGetSymbolAddress((void**)&p_G,    g_G);
    cudaGetSymbolAddress((void**)&p_U,    g_U);
    cudaGetSymbolAddress((void**)&Hh,  g_Hh);  cudaGetSymbolAddress((void**)&Hl,  g_Hl);
    cudaGetSymbolAddress((void**)&UPh, g_UPh); cudaGetSymbolAddress((void**)&UPl, g_UPl);
    cudaGetSymbolAddress((void**)&GWh, g_GWh); cudaGetSymbolAddress((void**)&GWl, g_GWl);
    cudaGetSymbolAddress((void**)&Th,  g_Th);  cudaGetSymbolAddress((void**)&Tl,  g_Tl);
    cudaGetSymbolAddress((void**)&Wh,  g_Wh);  cudaGetSymbolAddress((void**)&Wl,  g_Wl);
    cudaGetSymbolAddress((void**)&FGh, g_FGh); cudaGetSymbolAddress((void**)&FGl, g_FGl);
    cudaGetSymbolAddress((void**)&FUh, g_FUh); cudaGetSymbolAddress((void**)&FUl, g_FUl);
    cudaGetSymbolAddress((void**)&FDh, g_FDh); cudaGetSymbolAddress((void**)&FDl, g_FDl);
    cudaGetSymbolAddress((void**)&Ah,  g_Ah);  cudaGetSymbolAddress((void**)&Al,  g_Al);

    cudaFuncSetAttribute(gemm_planes, cudaFuncAttributeMaxDynamicSharedMemorySize, SMEM_BYTES);

    auto gemm = [&](const __nv_bfloat16* ah, const __nv_bfloat16* al, int lda,
                    const __nv_bfloat16* bh, const __nv_bfloat16* bl, int ldb,
                    float* C, int ldc, int M, int N, int K, int accum) {
        int blocks = (M / 128) * (N / 128);
        gemm_planes<<<blocks, 256, SMEM_BYTES>>>(ah, al, lda, bh, bl, ldb, C, ldc, M, N, K, accum);
    };
    auto split = [&](const float* s, __nv_bfloat16* h, __nv_bfloat16* l, size_t n) {
        split_kernel<<<(int)(n / 4 / 256), 256>>>(s, h, l);
    };

    // one-time splits (ordered so launch #6 — ncu's -s 5 -c 1 capture — is the big FFN GEMM)
    split(hidden, Hh, Hl, (size_t)MD * HD);                    // 1
    split(fg, FGh, FGl, (size_t)FD * HD);                      // 2
    split(fu, FUh, FUl, (size_t)FD * HD);                      // 3
    split(fd, FDh, FDl, (size_t)HD * FD);                      // 4
    split(up_w, UPh, UPl, (size_t)SD * HD);                    // 5
    gemm(Hh, Hl, HD, FGh, FGl, HD, p_G, FD, MD, FD, HD, 0);    // 6: FFN gate (profiled)
    split(gate_w, GWh, GWl, (size_t)SD * HD);                  // 7
    gemm(Hh, Hl, HD, FUh, FUl, HD, p_U, FD, MD, FD, HD, 0);    // 8: FFN up
    gemm(Hh, Hl, HD, UPh, UPl, HD, p_up, SD, MD, SD, HD, 0);   // 9: approx_up
    gemm(Hh, Hl, HD, GWh, GWl, HD, p_gate, SD, MD, SD, HD, 0); // 10: gate_pre
    build_T_kernel<<<(MD * SD) / 256, 256>>>(lp);              // 11
    pack_W_kernel<<<HD, 256>>>(la, fw);                        // 12
    gemm(Th, Tl, KT, Wh, Wl, KT, out, HD, MD, HD, KT, 0);      // 13: approx_out -> out
    act_kernel<<<(int)(((size_t)MD * FD) / 256), 256>>>();     // 14: silu(G)*U -> act planes
    gemm(Ah, Al, FD, FDh, FDl, FD, out, HD, MD, HD, FD, 1);    // 15: FFN down, accum into out
}

// round 10
// speedup vs baseline: 1.5409x; 1.1252x over previous
#include <cuda_runtime.h>
#include <cuda_bf16.h>
#include <cstdint>

// Problem dims (fixed by the reference)
#define MD 4096   // B*T
#define HD 4096   // hidden
#define SD 1024   // sampled intermediate
#define FD 9984   // ffn intermediate
#define GD 6      // taylor orders
#define KT 7168   // (G+1)*S concat-K for the fused Taylor GEMM

// -------- device scratch (no cudaMalloc allowed) --------
__device__ float g_up  [(size_t)MD * SD];
__device__ float g_gate[(size_t)MD * SD];
__device__ float g_G   [(size_t)MD * FD];
__device__ float g_U   [(size_t)MD * FD];
__device__ __align__(16) __nv_bfloat16 g_Hh [(size_t)MD * HD];
__device__ __align__(16) __nv_bfloat16 g_Hl [(size_t)MD * HD];
__device__ __align__(16) __nv_bfloat16 g_UPh[(size_t)SD * HD];
__device__ __align__(16) __nv_bfloat16 g_UPl[(size_t)SD * HD];
__device__ __align__(16) __nv_bfloat16 g_GWh[(size_t)SD * HD];
__device__ __align__(16) __nv_bfloat16 g_GWl[(size_t)SD * HD];
__device__ __align__(16) __nv_bfloat16 g_Th [(size_t)MD * KT];
__device__ __align__(16) __nv_bfloat16 g_Tl [(size_t)MD * KT];
__device__ __align__(16) __nv_bfloat16 g_Wh [(size_t)HD * KT];
__device__ __align__(16) __nv_bfloat16 g_Wl [(size_t)HD * KT];
__device__ __align__(16) __nv_bfloat16 g_FGh[(size_t)FD * HD];
__device__ __align__(16) __nv_bfloat16 g_FGl[(size_t)FD * HD];
__device__ __align__(16) __nv_bfloat16 g_FUh[(size_t)FD * HD];
__device__ __align__(16) __nv_bfloat16 g_FUl[(size_t)FD * HD];
__device__ __align__(16) __nv_bfloat16 g_FDh[(size_t)HD * FD];
__device__ __align__(16) __nv_bfloat16 g_FDl[(size_t)HD * FD];
__device__ __align__(16) __nv_bfloat16 g_Ah [(size_t)MD * FD];
__device__ __align__(16) __nv_bfloat16 g_Al [(size_t)MD * FD];

// ======================= helpers =======================
__device__ __forceinline__ uint32_t smem_u32(const void* p) {
    uint32_t a;
    asm("{ .reg .u64 t; cvta.to.shared.u64 t, %1; cvt.u32.u64 %0, t; }" : "=r"(a) : "l"(p));
    return a;
}
__device__ __forceinline__ void cpa16(uint32_t dst, const void* src) {
    asm volatile("cp.async.cg.shared.global [%0], [%1], 16;" :: "r"(dst), "l"(src));
}
#define CP_COMMIT() asm volatile("cp.async.commit_group;" ::: "memory")
#define CP_WAIT2()  asm volatile("cp.async.wait_group 2;" ::: "memory")

__device__ __forceinline__ void mma16(float* d, const uint32_t* a, const uint32_t* b) {
    asm volatile(
        "mma.sync.aligned.m16n8k16.row.col.f32.bf16.bf16.f32 "
        "{%0,%1,%2,%3}, {%4,%5,%6,%7}, {%8,%9}, {%0,%1,%2,%3};\n"
        : "+f"(d[0]), "+f"(d[1]), "+f"(d[2]), "+f"(d[3])
        : "r"(a[0]), "r"(a[1]), "r"(a[2]), "r"(a[3]), "r"(b[0]), "r"(b[1]));
}
__device__ __forceinline__ void ldm4(uint32_t* d, uint32_t addr) {
    asm volatile("ldmatrix.sync.aligned.m8n8.x4.shared.b16 {%0,%1,%2,%3}, [%4];"
        : "=r"(d[0]), "=r"(d[1]), "=r"(d[2]), "=r"(d[3]) : "r"(addr));
}
__device__ __forceinline__ void wsplit(__nv_bfloat16* hp, __nv_bfloat16* lp, size_t idx, float v) {
    __nv_bfloat16 h = __float2bfloat16_rn(v);
    hp[idx] = h;
    lp[idx] = __float2bfloat16_rn(v - __bfloat162float(h));
}

// ======================= bf16x3 GEMM on pre-split planes =======================
// C[M,N] (+)= A[M,K] * B[N,K]^T; A,B bf16 hi/lo planes, C fp32.
// D += Ahi*Bhi + Ahi*Blo + Alo*Bhi. 128x128 tile, BK=32, 4-stage cp.async,
// ldmatrix.x4 fragment loads, padded smem rows (LDSW=20 words) — LDSM conflict-free.
#define BK 32
#define LDSW 20                     // 16 data words (32 bf16) + 4 pad (80B row stride)
#define PLW (128 * LDSW)            // words per plane = 2560
#define PLB (PLW * 4)               // bytes per plane = 10240
#define STW (4 * PLW)               // words per stage (Ahi,Alo,Bhi,Blo)
#define STB (STW * 4)               // bytes per stage = 40960
#define NSTAGE 4
#define SMEM_BYTES (NSTAGE * STB)   // 163840

__global__ void __launch_bounds__(256, 1)
gemm_planes(const __nv_bfloat16* __restrict__ Ah, const __nv_bfloat16* __restrict__ Al, int lda,
            const __nv_bfloat16* __restrict__ Bh, const __nv_bfloat16* __restrict__ Bl, int ldb,
            float* __restrict__ C, int ldc, int M, int N, int K, int accumulate) {
    extern __shared__ uint32_t smw[];
    const uint32_t sbase = smem_u32(smw);
    const int tid = threadIdx.x;

    // L2-friendly tile rasterization (GROUP along M)
    const int grid_m = M / 128, grid_n = N / 128;
    const int GROUP = 16;
    int pid   = blockIdx.x;
    int width = GROUP * grid_n;
    int group = pid / width;
    int first = group * GROUP;
    int gsz   = min(GROUP, grid_m - first);
    int tm    = first + (pid % gsz);
    int tn    = (pid % width) / gsz;
    const int m0 = tm * 128, n0 = tn * 128;

    // cp.async fill mapping: row = tid>>1 (0..127), half = tid&1 (2 x 16B per plane)
    const int frow = tid >> 1;
    const int fhalf = tid & 1;
    const __nv_bfloat16* pAh = Ah + (size_t)(m0 + frow) * lda + fhalf * 16;
    const __nv_bfloat16* pAl = Al + (size_t)(m0 + frow) * lda + fhalf * 16;
    const __nv_bfloat16* pBh = Bh + (size_t)(n0 + frow) * ldb + fhalf * 16;
    const __nv_bfloat16* pBl = Bl + (size_t)(n0 + frow) * ldb + fhalf * 16;
    const uint32_t dstw0 = (frow * LDSW + fhalf * 8) * 4;   // byte offset within plane

    const int Kt = K / BK;

    auto issue = [&](int kt) {
        const int k0 = kt * BK;
        uint32_t d = sbase + (kt & (NSTAGE - 1)) * STB + dstw0;
        cpa16(d, pAh + k0);            cpa16(d + 16, pAh + k0 + 8);
        d += PLB;
        cpa16(d, pAl + k0);            cpa16(d + 16, pAl + k0 + 8);
        d += PLB;
        cpa16(d, pBh + k0);            cpa16(d + 16, pBh + k0 + 8);
        d += PLB;
        cpa16(d, pBl + k0);            cpa16(d + 16, pBl + k0 + 8);
    };

    issue(0); CP_COMMIT();
    issue(1); CP_COMMIT();
    issue(2); CP_COMMIT();

    const int lane = tid & 31;
    const int warp = tid >> 5;
    const int wm = (warp & 1) * 64;   // 2 warps along M -> 64 rows each
    const int wn = (warp >> 1) * 32;  // 4 warps along N -> 32 cols each
    const int r  = lane >> 2;
    const int cc = lane & 3;
    const int r8 = lane & 7;
    const int quad = lane >> 3;

    // ldmatrix per-lane byte offsets within a plane
    // A x4 (per mf): m0-7/k0-7, m8-15/k0-7, m0-7/k8-15, m8-15/k8-15
    uint32_t aOffm[4];
#pragma unroll
    for (int mf = 0; mf < 4; mf++)
        aOffm[mf] = (uint32_t)((wm + mf * 16 + r8 + (quad & 1) * 8) * 80 + (quad >> 1) * 16);
    // B x4 (per nf pair p,p+1): b0(nf_p), b1(nf_p), b0(nf_p+1), b1(nf_p+1)
    uint32_t bOffp[2];
#pragma unroll
    for (int pi = 0; pi < 2; pi++)
        bOffp[pi] = (uint32_t)((wn + (pi * 2 + (quad >> 1)) * 8 + r8) * 80 + (quad & 1) * 16);

    float acc[4][4][4];
#pragma unroll
    for (int i = 0; i < 4; i++)
#pragma unroll
        for (int j = 0; j < 4; j++)
#pragma unroll
            for (int k = 0; k < 4; k++) acc[i][j][k] = 0.f;

    for (int kt = 0; kt < Kt; kt++) {
        CP_WAIT2();              // stage kt complete (<=2 newer groups pending)
        __syncthreads();         // all warps done reading stage kt-1 (buffer (kt+3)%4)
        if (kt + 3 < Kt) issue(kt + 3);
        CP_COMMIT();             // exactly one group per iteration

        const uint32_t sb = sbase + (kt & (NSTAGE - 1)) * STB;
#pragma unroll
        for (int kk = 0; kk < 2; kk++) {   // two k16 chunks per BK=32
            const uint32_t ko = kk * 32;   // 16 bf16 = 32 bytes
            uint32_t afh[4][4], afl[4][4], bfh[8], bfl[8];
#pragma unroll
            for (int mf = 0; mf < 4; mf++) {
                ldm4(afh[mf], sb + aOffm[mf] + ko);
                ldm4(afl[mf], sb + PLB + aOffm[mf] + ko);
            }
#pragma unroll
            for (int pi = 0; pi < 2; pi++) {
                ldm4(&bfh[pi * 4], sb + 2 * PLB + bOffp[pi] + ko);
                ldm4(&bfl[pi * 4], sb + 3 * PLB + bOffp[pi] + ko);
            }
#pragma unroll
            for (int mf = 0; mf < 4; mf++)
#pragma unroll
                for (int nf = 0; nf < 4; nf++) {
                    mma16(acc[mf][nf], afh[mf], &bfh[nf * 2]);   // hi*hi
                    mma16(acc[mf][nf], afh[mf], &bfl[nf * 2]);   // hi*lo
                    mma16(acc[mf][nf], afl[mf], &bfh[nf * 2]);   // lo*hi
                }
        }
    }

    // epilogue (m16n8 f32 accumulator layout)
#pragma unroll
    for (int mf = 0; mf < 4; mf++) {
#pragma unroll
        for (int nf = 0; nf < 4; nf++) {
            int grow = m0 + wm + mf * 16 + r;
            int gcol = n0 + wn + nf * 8 + cc * 2;
            float* c0 = C + (size_t)grow * ldc + gcol;
            float* c1 = C + (size_t)(grow + 8) * ldc + gcol;
            if (accumulate) {
                float2 v0 = *reinterpret_cast<float2*>(c0);
                float2 v1 = *reinterpret_cast<float2*>(c1);
                v0.x += acc[mf][nf][0]; v0.y += acc[mf][nf][1];
                v1.x += acc[mf][nf][2]; v1.y += acc[mf][nf][3];
                *reinterpret_cast<float2*>(c0) = v0;
                *reinterpret_cast<float2*>(c1) = v1;
            } else {
                *reinterpret_cast<float2*>(c0) = make_float2(acc[mf][nf][0], acc[mf][nf][1]);
                *reinterpret_cast<float2*>(c1) = make_float2(acc[mf][nf][2], acc[mf][nf][3]);
            }
        }
    }
}

// -------- one-time fp32 -> bf16 hi/lo plane split (vectorized) --------
__global__ void split_kernel(const float* __restrict__ src,
                             __nv_bfloat16* __restrict__ hi,
                             __nv_bfloat16* __restrict__ lo) {
    size_t i = ((size_t)blockIdx.x * 256 + threadIdx.x) * 4;
    float4 v = *reinterpret_cast<const float4*>(src + i);
    __nv_bfloat16 h0 = __float2bfloat16_rn(v.x), h1 = __float2bfloat16_rn(v.y);
    __nv_bfloat16 h2 = __float2bfloat16_rn(v.z), h3 = __float2bfloat16_rn(v.w);
    __nv_bfloat16 l0 = __float2bfloat16_rn(v.x - __bfloat162float(h0));
    __nv_bfloat16 l1 = __float2bfloat16_rn(v.y - __bfloat162float(h1));
    __nv_bfloat16 l2 = __float2bfloat16_rn(v.z - __bfloat162float(h2));
    __nv_bfloat16 l3 = __float2bfloat16_rn(v.w - __bfloat162float(h3));
    __nv_bfloat162 H0(h0, h1), H1(h2, h3), L0(l0, l1), L1(l2, l3);
    *reinterpret_cast<uint2*>(hi + i) =
        make_uint2(*reinterpret_cast<uint32_t*>(&H0), *reinterpret_cast<uint32_t*>(&H1));
    *reinterpret_cast<uint2*>(lo + i) =
        make_uint2(*reinterpret_cast<uint32_t*>(&L0), *reinterpret_cast<uint32_t*>(&L1));
}

// -------- build Tcat planes: T[bt, g*S+s] = (delta^g / g!) * approx_up (cutoff g=5,6) --------
__global__ void build_T_kernel(const float* __restrict__ lp) {
    int i = blockIdx.x * blockDim.x + threadIdx.x;   // over MD*SD
    int s  = i & (SD - 1);
    int bt = i >> 10;
    size_t base = (size_t)bt * KT + s;
    float au = g_up[i];
    float d  = g_gate[i] - lp[s];
    float keep = (fabsf(d) <= 2.5f) ? 1.0f : 0.0f;
    float p = 1.0f;
    wsplit(g_Th, g_Tl, base, au);                                  // order 0
    p *= d;                wsplit(g_Th, g_Tl, base + 1 * SD, p * au);
    p *= d * 0.5f;         wsplit(g_Th, g_Tl, base + 2 * SD, p * au);
    p *= d * (1.f / 3.f);  wsplit(g_Th, g_Tl, base + 3 * SD, p * au);
    p *= d * 0.25f;        wsplit(g_Th, g_Tl, base + 4 * SD, p * au);
    p *= d * 0.2f;         wsplit(g_Th, g_Tl, base + 5 * SD, p * au * keep);
    p *= d * (1.f / 6.f);  wsplit(g_Th, g_Tl, base + 6 * SD, p * au * keep);
}

// -------- pack Wcat planes: g=0 -> local_approx_output[h,s]; g>=1 -> fuse_weight[h,s,g-1] --------
__global__ void pack_W_kernel(const float* __restrict__ la, const float* __restrict__ fw) {
    int h = blockIdx.x;
    __shared__ float tile[SD * GD];   // 24KB
    const float* src = fw + (size_t)h * SD * GD;
    for (int i = threadIdx.x; i < SD * GD; i += blockDim.x) tile[i] = src[i];   // coalesced
    size_t dstb = (size_t)h * KT;
    for (int i = threadIdx.x; i < SD; i += blockDim.x)
        wsplit(g_Wh, g_Wl, dstb + i, la[(size_t)h * SD + i]);
    __syncthreads();
    for (int j = threadIdx.x; j < SD * GD; j += blockDim.x) {
        int g = j >> 10, s = j & (SD - 1);
        wsplit(g_Wh, g_Wl, dstb + SD + j, tile[s * GD + g]);
    }
}

// -------- act planes: silu(G) * U --------
__global__ void act_kernel() {
    size_t i = (size_t)blockIdx.x * blockDim.x + threadIdx.x;
    float g = g_G[i], u = g_U[i];
    float v = u * g / (1.0f + __expf(-g));
    wsplit(g_Ah, g_Al, i, v);
}

// -------- launcher --------
extern "C" void kernel_launch(void* const* d_in, const int* in_sizes, int n_in,
                              void* d_out, int out_size) {
    (void)in_sizes; (void)n_in; (void)out_size;
    const float* hidden = (const float*)d_in[0];   // [B,T,H]
    const float* up_w   = (const float*)d_in[1];   // [S,H]
    const float* gate_w = (const float*)d_in[2];   // [S,H]
    const float* lp     = (const float*)d_in[3];   // [S]
    const float* la     = (const float*)d_in[4];   // [H,S]
    const float* fw     = (const float*)d_in[5];   // [H,S,G]
    // d_in[6] = discount_factor: factorials computed directly
    const float* fg     = (const float*)d_in[7];   // [F,H]
    const float* fu     = (const float*)d_in[8];   // [F,H]
    const float* fd     = (const float*)d_in[9];   // [H,F]
    float* out = (float*)d_out;                    // [B,T,H] fp32

    float *p_up, *p_gate, *p_G, *p_U;
    __nv_bfloat16 *Hh, *Hl, *UPh, *UPl, *GWh, *GWl, *Th, *Tl, *Wh, *Wl;
    __nv_bfloat16 *FGh, *FGl, *FUh, *FUl, *FDh, *FDl, *Ah, *Al;
    cudaGetSymbolAddress((void**)&p_up,   g_up);
    cudaGetSymbolAddress((void**)&p_gate, g_gate);
    cudaGetSymbolAddress((void**)&p_G,    g_G);
    cudaGetSymbolAddress((void**)&p_U,    g_U);
    cudaGetSymbolAddress((void**)&Hh,  g_Hh);  cudaGetSymbolAddress((void**)&Hl,  g_Hl);
    cudaGetSymbolAddress((void**)&UPh, g_UPh); cudaGetSymbolAddress((void**)&UPl, g_UPl);
    cudaGetSymbolAddress((void**)&GWh, g_GWh); cudaGetSymbolAddress((void**)&GWl, g_GWl);
    cudaGetSymbolAddress((void**)&Th,  g_Th);  cudaGetSymbolAddress((void**)&Tl,  g_Tl);
    cudaGetSymbolAddress((void**)&Wh,  g_Wh);  cudaGetSymbolAddress((void**)&Wl,  g_Wl);
    cudaGetSymbolAddress((void**)&FGh, g_FGh); cudaGetSymbolAddress((void**)&FGl, g_FGl);
    cudaGetSymbolAddress((void**)&FUh, g_FUh); cudaGetSymbolAddress((void**)&FUl, g_FUl);
    cudaGetSymbolAddress((void**)&FDh, g_FDh); cudaGetSymbolAddress((void**)&FDl, g_FDl);
    cudaGetSymbolAddress((void**)&Ah,  g_Ah);  cudaGetSymbolAddress((void**)&Al,  g_Al);

    cudaFuncSetAttribute(gemm_planes, cudaFuncAttributeMaxDynamicSharedMemorySize, SMEM_BYTES);

    auto gemm = [&](const __nv_bfloat16* ah, const __nv_bfloat16* al, int lda,
                    const __nv_bfloat16* bh, const __nv_bfloat16* bl, int ldb,
                    float* C, int ldc, int M, int N, int K, int accum) {
        int blocks = (M / 128) * (N / 128);
        gemm_planes<<<blocks, 256, SMEM_BYTES>>>(ah, al, lda, bh, bl, ldb, C, ldc, M, N, K, accum);
    };
    auto split = [&](const float* s, __nv_bfloat16* h, __nv_bfloat16* l, size_t n) {
        split_kernel<<<(int)(n / 4 / 256), 256>>>(s, h, l);
    };

    // launch order puts the big FFN GEMM at index 3 (ncu -s 5 -c 1 lands there)
    split(hidden, Hh, Hl, (size_t)MD * HD);                    // 0
    split(fg, FGh, FGl, (size_t)FD * HD);                      // 1
    split(fu, FUh, FUl, (size_t)FD * HD);                      // 2
    gemm(Hh, Hl, HD, FGh, FGl, HD, p_G, FD, MD, FD, HD, 0);    // 3: FFN gate (profile target)
    gemm(Hh, Hl, HD, FUh, FUl, HD, p_U, FD, MD, FD, HD, 0);    // 4: FFN up
    split(up_w, UPh, UPl, (size_t)SD * HD);                    // 5
    gemm(Hh, Hl, HD, UPh, UPl, HD, p_up, SD, MD, SD, HD, 0);   // 6: approx_up
    split(gate_w, GWh, GWl, (size_t)SD * HD);                  // 7
    gemm(Hh, Hl, HD, GWh, GWl, HD, p_gate, SD, MD, SD, HD, 0); // 8: gate_pre
    split(fd, FDh, FDl, (size_t)HD * FD);                      // 9
    build_T_kernel<<<(MD * SD) / 256, 256>>>(lp);              // 10
    pack_W_kernel<<<HD, 256>>>(la, fw);                        // 11
    gemm(Th, Tl, KT, Wh, Wl, KT, out, HD, MD, HD, KT, 0);      // 12: approx_out -> out
    act_kernel<<<(int)(((size_t)MD * FD) / 256), 256>>>();     // 13: silu(G)*U -> act planes
    gemm(Ah, Al, FD, FDh, FDl, FD, out, HD, MD, HD, FD, 1);    // 14: FFN down, accum into out
}